// round 16
// baseline (speedup 1.0000x reference)
#include <cuda_runtime.h>
#include <cuda_fp16.h>
#include <cstdint>

// ---------------------------------------------------------------------------
// Problem constants
// ---------------------------------------------------------------------------
constexpr int kB = 2;
constexpr int kM = 4096;
constexpr int kC = 256;
constexpr int kH = 64;
constexpr int kW = 64;
constexpr int kLevels = 4;
constexpr int kRad = 4;
constexpr int kSide = 9;
constexpr int kFeat = kLevels * kSide * kSide;          // 324
constexpr int kP    = 4096 + 1024 + 256 + 64;           // 5440 positions / batch
constexpr int kPPad = 5632;                             // 22 * 256 (N padded)
constexpr int kNGRP = 22;                               // N groups of 256

// Static device scratch (zero-initialized; pad rows stay zero)
__device__ __half g_pyrh[(size_t)kB * kPPad * kC];      // fp16 GEMM B operand (all levels)
__device__ __half g_f1h [(size_t)kB * kM * kC];         // fp16 GEMM A operand
__device__ __half g_corr[(size_t)kB * kM * kPPad];      // fp16 correlation pyramid

__constant__ int c_lvl_off[4] = {0, 4096, 5120, 5376};

// ---------------------------------------------------------------------------
// Helpers (baseline PTX only — nothing 'a'-gated; ptxas targets sm_103)
// ---------------------------------------------------------------------------
__device__ __forceinline__ uint32_t smem_u32(const void* p) {
    uint32_t a;
    asm("{ .reg .u64 t; cvta.to.shared.u64 t, %1; cvt.u32.u64 %0, t; }" : "=r"(a) : "l"(p));
    return a;
}
__device__ __forceinline__ void cp16(uint32_t dst, const void* src) {
    asm volatile("cp.async.cg.shared.global [%0], [%1], 16;" :: "r"(dst), "l"(src));
}
__device__ __forceinline__ void cp_commit() { asm volatile("cp.async.commit_group;" ::: "memory"); }
__device__ __forceinline__ void cp_wait1()  { asm volatile("cp.async.wait_group 1;" ::: "memory"); }
__device__ __forceinline__ void cp_wait0()  { asm volatile("cp.async.wait_group 0;" ::: "memory"); }
__device__ __forceinline__ void mma16816(float* c, const uint32_t* a, const uint32_t* b) {
    asm volatile(
        "mma.sync.aligned.m16n8k16.row.col.f32.f16.f16.f32 "
        "{%0,%1,%2,%3}, {%4,%5,%6,%7}, {%8,%9}, {%0,%1,%2,%3};"
        : "+f"(c[0]), "+f"(c[1]), "+f"(c[2]), "+f"(c[3])
        : "r"(a[0]), "r"(a[1]), "r"(a[2]), "r"(a[3]), "r"(b[0]), "r"(b[1]));
}
__device__ __forceinline__ void ldm_x4(uint32_t* r, uint32_t addr) {
    asm volatile("ldmatrix.sync.aligned.m8n8.x4.shared.b16 {%0,%1,%2,%3}, [%4];"
                 : "=r"(r[0]), "=r"(r[1]), "=r"(r[2]), "=r"(r[3]) : "r"(addr));
}

// ---------------------------------------------------------------------------
// Kernel 1 (fused): transpose fmap2 (B,C,H,W) -> (B,pos,C) fp16 level 0,
// AND fmap1 fp32 -> fp16 (blocks >= 2048 do the convert).
// ---------------------------------------------------------------------------
__global__ void k_prep(const float* __restrict__ fmap2, const float4* __restrict__ f1) {
    if (blockIdx.x >= 2048) {
        int i = (blockIdx.x - 2048) * 1024 + threadIdx.y * 32 + threadIdx.x;
        float4 v = f1[i];
        __half2 a = __floats2half2_rn(v.x, v.y);
        __half2 b = __floats2half2_rn(v.z, v.w);
        uint2 u;
        u.x = *reinterpret_cast<uint32_t*>(&a);
        u.y = *reinterpret_cast<uint32_t*>(&b);
        reinterpret_cast<uint2*>(g_f1h)[i] = u;
        return;
    }
    __shared__ float s[32][33];
    int bidx = blockIdx.x;
    int ct = bidx & 7;  bidx >>= 3;
    int xt = bidx & 1;  bidx >>= 1;
    int y  = bidx & 63; bidx >>= 6;
    int b  = bidx;
    int tx = threadIdx.x, ty = threadIdx.y;
    s[ty][tx] = fmap2[(((size_t)b * kC + ct * 32 + ty) * kH + y) * kW + (xt * 32 + tx)];
    __syncthreads();
    float v = s[tx][ty];
    size_t o = ((size_t)b * kPPad + (size_t)y * kW + (xt * 32 + ty)) * kC + (ct * 32 + tx);
    g_pyrh[o] = __float2half(v);
}

// ---------------------------------------------------------------------------
// Kernel 2 (fused): build pyramid levels 1..3 in one launch, sourcing the
// fp16 level-0 (fp32 arithmetic in smem).
// ---------------------------------------------------------------------------
__global__ void __launch_bounds__(256) k_pool_fused() {
    __shared__ float s0[256][33];
    __shared__ float s1[64][33];
    __shared__ float s2[16][33];

    int bidx = blockIdx.x;
    int cc = bidx & 7;  bidx >>= 3;
    int xt = bidx & 3;  bidx >>= 2;
    int yt = bidx & 3;  bidx >>= 2;
    int b  = bidx;
    int tid = threadIdx.x;

    const __half* src = g_pyrh + ((size_t)b * kPPad) * kC + cc * 32;
    #pragma unroll
    for (int j = 0; j < 4; j++) {
        int idx = tid + j * 256;        // 1024 uint4 (8 halves each)
        int pos = idx >> 2, cseg = idx & 3;
        int py = pos >> 4, px = pos & 15;
        uint4 u = *reinterpret_cast<const uint4*>(
            src + ((size_t)(yt * 16 + py) * kW + (xt * 16 + px)) * kC + cseg * 8);
        const __half2* h2 = reinterpret_cast<const __half2*>(&u);
        #pragma unroll
        for (int k2 = 0; k2 < 4; k2++) {
            float2 f = __half22float2(h2[k2]);
            s0[pos][cseg * 8 + k2 * 2 + 0] = f.x;
            s0[pos][cseg * 8 + k2 * 2 + 1] = f.y;
        }
    }
    __syncthreads();

    {
        int pos1 = tid >> 2;
        int c0 = (tid & 3) * 8;
        int y1 = pos1 >> 3, x1 = pos1 & 7;
        int pa = (2 * y1) * 16 + 2 * x1;
        __half h[8];
        #pragma unroll
        for (int c = 0; c < 8; c++) {
            float v = 0.25f * (s0[pa][c0 + c] + s0[pa + 1][c0 + c] +
                               s0[pa + 16][c0 + c] + s0[pa + 17][c0 + c]);
            s1[pos1][c0 + c] = v;
            h[c] = __float2half(v);
        }
        size_t o = ((size_t)b * kPPad + 4096 + (size_t)(yt * 8 + y1) * 32 + (xt * 8 + x1)) * kC
                 + cc * 32 + c0;
        *reinterpret_cast<uint4*>(g_pyrh + o) = *reinterpret_cast<uint4*>(h);
    }
    __syncthreads();

    if (tid < 128) {
        int pos2 = tid >> 3;
        int c0 = (tid & 7) * 4;
        int y2 = pos2 >> 2, x2 = pos2 & 3;
        int pa = (2 * y2) * 8 + 2 * x2;
        __half h[4];
        #pragma unroll
        for (int c = 0; c < 4; c++) {
            float v = 0.25f * (s1[pa][c0 + c] + s1[pa + 1][c0 + c] +
                               s1[pa + 8][c0 + c] + s1[pa + 9][c0 + c]);
            s2[pos2][c0 + c] = v;
            h[c] = __float2half(v);
        }
        size_t o = ((size_t)b * kPPad + 5120 + (size_t)(yt * 4 + y2) * 16 + (xt * 4 + x2)) * kC
                 + cc * 32 + c0;
        *reinterpret_cast<uint2*>(g_pyrh + o) = *reinterpret_cast<uint2*>(h);
    }
    __syncthreads();

    if (tid < 128) {
        int pos3 = tid >> 5;
        int c = tid & 31;
        int y3 = pos3 >> 1, x3 = pos3 & 1;
        int pa = (2 * y3) * 4 + 2 * x3;
        float v = 0.25f * (s2[pa][c] + s2[pa + 1][c] + s2[pa + 4][c] + s2[pa + 5][c]);
        size_t o = ((size_t)b * kPPad + 5376 + (size_t)(yt * 2 + y3) * 8 + (xt * 2 + x3)) * kC
                 + cc * 32 + c;
        g_pyrh[o] = __float2half(v);
    }
}

// ---------------------------------------------------------------------------
// Kernel 3: HMMA GEMM  corr[b, m, p] = sum_c f1h[b,m,c] * pyrh[b,p,c]
// CTA tile 128(M) x 256(N), warp tile 64x64 (2M x 4N warps), K=256.
// A resident (64KB swizzled); B: 3-stage ring of 32KB chunks (256n x 64k),
// one barrier per chunk, prefetch distance 2, single epilogue. 1 CTA/SM.
// ---------------------------------------------------------------------------
constexpr int kABytes = 128 * 512;                      // 65536, swizzled
constexpr int kBChunkBytes = 256 * 128;                 // 32768, swizzled
constexpr int kGemmSmem = kABytes + 3 * kBChunkBytes;   // 163840

__device__ __forceinline__ void issueB(uint32_t sB, int tid, int b, int pbase, int kc) {
    const __half* src0 = g_pyrh + ((size_t)b * kPPad + pbase) * kC + kc * 64;
    #pragma unroll
    for (int j = 0; j < 8; j++) {
        int i = tid + j * 256;          // 2048 x 16B
        int n = i >> 3, seg = i & 7;
        cp16(sB + n * 128 + ((seg ^ (n & 7)) << 4), src0 + (size_t)n * kC + seg * 8);
    }
}

__global__ void __launch_bounds__(256, 1) k_gemm() {
    extern __shared__ char smem[];
    uint32_t sAu = smem_u32(smem);
    uint32_t sBu[3] = {sAu + kABytes, sAu + kABytes + kBChunkBytes,
                       sAu + kABytes + 2 * kBChunkBytes};

    int tid  = threadIdx.x;
    int wid  = tid >> 5, lane = tid & 31;
    int g    = lane >> 2;
    int t2   = (lane & 3) * 2;
    int wm   = wid & 1;                 // 2 warps along M (64 rows each)
    int wn   = wid >> 1;                // 4 warps along N (64 cols each)

    int ngrp  = blockIdx.x;             // 0..21 (N groups of 256)
    int mtile = blockIdx.y;             // 0..31
    int b     = blockIdx.z;             // 0..1

    int lrow  = (lane & 7) + ((lane >> 3) & 1) * 8;
    int ulane = (lane >> 4) & 1;

    uint32_t aRow[4]; int aX[4];
    #pragma unroll
    for (int mf = 0; mf < 4; mf++) {
        int r = wm * 64 + mf * 16 + lrow;
        aRow[mf] = sAu + r * 512;
        aX[mf] = r & 7;
    }
    uint32_t bRow[4]; int bX[4];
    #pragma unroll
    for (int ng = 0; ng < 4; ng++) {
        int n = wn * 64 + ng * 16 + lrow;
        bRow[ng] = n * 128;
        bX[ng] = n & 7;
    }

    // ---- prologue: A resident + first two B chunks ----
    {
        const __half* srcA = g_f1h + ((size_t)b * kM + (size_t)mtile * 128) * kC;
        #pragma unroll
        for (int j = 0; j < 16; j++) {
            int i = tid + j * 256;
            int r = i >> 5, seg = i & 31;
            cp16(sAu + r * 512 + ((seg ^ (r & 7)) << 4), srcA + (size_t)r * kC + seg * 8);
        }
        issueB(sBu[0], tid, b, ngrp * 256, 0);
        cp_commit();                    // group: A + chunk0
        issueB(sBu[1], tid, b, ngrp * 256, 1);
        cp_commit();                    // group: chunk1
    }

    float acc[4][8][4];
    #pragma unroll
    for (int mf = 0; mf < 4; mf++)
        #pragma unroll
        for (int nf = 0; nf < 8; nf++)
            #pragma unroll
            for (int i = 0; i < 4; i++) acc[mf][nf][i] = 0.0f;

    #pragma unroll 1
    for (int j = 0; j < 4; j++) {
        if (j == 3) cp_wait0(); else cp_wait1();
        __syncthreads();

        if (j + 2 < 4) {
            int bn = j + 2;             // ring index == chunk index (4 chunks, 3 bufs: j+2<4 -> bn 2,3%3=0)
            if (bn >= 3) bn -= 3;
            issueB(sBu[bn], tid, b, ngrp * 256, j + 2);
            cp_commit();
        }

        uint32_t sBc = sBu[j >= 3 ? j - 3 : j];

        #pragma unroll
        for (int ks = 0; ks < 4; ks++) {
            int uA = j * 8 + ks * 2 + ulane;
            int uB = ks * 2 + ulane;
            uint32_t af[4][4], bq[4][4];
            #pragma unroll
            for (int mf = 0; mf < 4; mf++)
                ldm_x4(af[mf], aRow[mf] + ((uA ^ aX[mf]) << 4));
            #pragma unroll
            for (int ng = 0; ng < 4; ng++)
                ldm_x4(bq[ng], sBc + bRow[ng] + ((uB ^ bX[ng]) << 4));
            #pragma unroll
            for (int mf = 0; mf < 4; mf++)
                #pragma unroll
                for (int nf = 0; nf < 8; nf++) {
                    uint32_t bfr[2] = {bq[nf >> 1][nf & 1], bq[nf >> 1][2 + (nf & 1)]};
                    mma16816(acc[mf][nf], af[mf], bfr);
                }
        }
    }

    // ---- single epilogue: 128x256 fp16 ----
    __half* epiBase = g_corr + ((size_t)b * kM + mtile * 128 + wm * 64 + g) * kPPad
                    + ngrp * 256 + wn * 64 + t2;
    #pragma unroll
    for (int mf = 0; mf < 4; mf++) {
        __half* row0 = epiBase + (size_t)(mf * 16) * kPPad;
        __half* row1 = row0 + 8 * kPPad;
        #pragma unroll
        for (int nf = 0; nf < 8; nf++) {
            __half2 v01 = __floats2half2_rn(acc[mf][nf][0], acc[mf][nf][1]);
            __half2 v23 = __floats2half2_rn(acc[mf][nf][2], acc[mf][nf][3]);
            *reinterpret_cast<__half2*>(row0 + nf * 8) = v01;
            *reinterpret_cast<__half2*>(row1 + nf * 8) = v23;
        }
    }
}

// ---------------------------------------------------------------------------
// Kernel 4: sampler. Block = (32 queries, ONE level); warp-per-query tap
// loads (lanes walk one query's 10x10 window), coalesced output stores.
// ---------------------------------------------------------------------------
__global__ void __launch_bounds__(128) k_sample(const float* __restrict__ coords,
                                                float* __restrict__ out) {
    __shared__ float Dsh[32][101];
    __shared__ float cxs[32], cys[32];

    int qt = blockIdx.x;                // 0..255
    int l  = blockIdx.y;                // 0..3
    int b  = qt >> 7;
    int m0 = (qt & 127) * 32;
    int tid = threadIdx.x;
    int lane = tid & 31;
    int w    = tid >> 5;                // 0..3

    if (tid < 32) {
        int q = b * kM + m0 + tid;
        cxs[tid] = coords[(size_t)q * 2 + 0];
        cys[tid] = coords[(size_t)q * 2 + 1];
    }
    __syncthreads();

    float scale = 1.0f / (float)(1 << l);
    int Wl = kW >> l, Hl = kH >> l;
    int loff = c_lvl_off[l];

    // tap phase: warp w loads queries w*8 .. w*8+7
    #pragma unroll
    for (int i = 0; i < 8; i++) {
        int qi = w * 8 + i;
        float qx = cxs[qi] * scale;
        float qy = cys[qi] * scale;
        int ix0 = (int)floorf(qx) - kRad;
        int iy0 = (int)floorf(qy) - kRad;
        const __half* crow = g_corr + (size_t)(b * kM + m0 + qi) * kPPad + loff;
        #pragma unroll
        for (int r = 0; r < 4; r++) {
            int p = r * 32 + lane;
            if (p < 100) {
                int py = p / 10, px = p - py * 10;
                int txp = ix0 + px, typ = iy0 + py;
                bool valid = ((unsigned)txp < (unsigned)Wl) & ((unsigned)typ < (unsigned)Hl);
                int off = typ * Wl + txp;
                off = off < 0 ? 0 : off;     // clamped address, value masked
                float v = valid ? __half2float(__ldg(crow + off)) : 0.0f;
                Dsh[qi][p] = v;
            }
        }
    }
    __syncthreads();

    // combine phase
    int qlocal = lane;
    float clx = cxs[qlocal] * scale;
    float cly = cys[qlocal] * scale;
    float fx0 = floorf(clx), fy0 = floorf(cly);
    float wx1 = clx - fx0, wx0 = 1.0f - wx1;
    float wy1 = cly - fy0, wy0 = 1.0f - wy1;

    float* obase = out + ((size_t)b * kFeat + l * 81) * kM + m0 + qlocal;
    #pragma unroll
    for (int it = 0; it < 21; it++) {
        int f = it * 4 + w;
        if (f < 81) {
            int ixo = f / 9;
            int iyo = f - ixo * 9;
            float d00 = Dsh[qlocal][iyo * 10 + ixo];
            float d01 = Dsh[qlocal][iyo * 10 + ixo + 1];
            float d10 = Dsh[qlocal][iyo * 10 + ixo + 10];
            float d11 = Dsh[qlocal][iyo * 10 + ixo + 11];
            float val = wy0 * (wx0 * d00 + wx1 * d01) + wy1 * (wx0 * d10 + wx1 * d11);
            obase[(size_t)f * kM] = val;
        }
    }
}

// ---------------------------------------------------------------------------
extern "C" void kernel_launch(void* const* d_in, const int* in_sizes, int n_in,
                              void* d_out, int out_size) {
    const float* fmap1  = (const float*)d_in[0];
    const float* fmap2  = (const float*)d_in[1];
    const float* coords = (const float*)d_in[2];
    float* out = (float*)d_out;

    k_prep<<<2048 + 512, dim3(32, 32)>>>(fmap2, (const float4*)fmap1);
    k_pool_fused<<<256, 256>>>();

    cudaFuncSetAttribute(k_gemm, cudaFuncAttributeMaxDynamicSharedMemorySize, kGemmSmem);
    k_gemm<<<dim3(kNGRP, kM / 128, kB), 256, kGemmSmem>>>();

    k_sample<<<dim3(256, 4), 128>>>(coords, out);
}